// round 15
// baseline (speedup 1.0000x reference)
#include <cuda_runtime.h>
#include <cuda_bf16.h>

#define CH 32
typedef unsigned long long ull;

// ---------------- packed fp32x2 helpers (exact fp32 math, 2 MACs/issue) ----------------
#define UNPACK_FF(a, b, in) \
    asm("mov.b64 {%0, %1}, %2;" : "=f"(a), "=f"(b) : "l"(in))
#define FMA2(d, a, b, c) \
    asm("fma.rn.f32x2 %0, %1, %2, %3;" : "=l"(d) : "l"(a), "l"(b), "l"(c))

// ---------------- device scratch (static: no allocation) ----------------
__device__ float g_q   [2 * CH * 4096];            // query field  [b][c][4096]
__device__ float g_k   [2 * 3 * CH * 4096];        // key fields   [b][i][c][4096]
__device__ float g_sraw[2 * CH * 48];              // raw sums: [b*32+c][i*16 + (0..7 skk | 8..15 sqk)]
__device__ float g_sqq [2 * CH];                   // ||Q||^2 per (b,c)
__device__ float g_V   [2 * 3 * CH * 65536];       // value fields [b][i][c][65536]
__device__ float g_pre [2 * CH * 65536];           // pre out-conv [b][c][65536]

__device__ __forceinline__ float warpReduce(float v) {
#pragma unroll
    for (int o = 16; o > 0; o >>= 1) v += __shfl_down_sync(0xffffffffu, v, o);
    return v;
}

// ================= Kernel A: k1(trans conv + Q/K epilogue)  ||  k3(value GEMMs) ================
// grid.x: [0,128) -> k1 body, [128,896) -> k3 body. 256 threads.
__global__ void __launch_bounds__(256) kA(const float* __restrict__ cen,
                                          const float* __restrict__ tw,
                                          const float* __restrict__ tb,
                                          const float* __restrict__ qW,
                                          const float* __restrict__ kW,
                                          const float* __restrict__ vW) {
    int tid = threadIdx.x;
    if (blockIdx.x < 128) {
        // ---------------- k1 body: 5x5 stride-4 conv, then Q/K 1x1 on the tile ----------------
        int bt   = blockIdx.x;
        int b    = bt >> 6;
        int tile = bt & 63;
        int ty0  = (tile >> 3) << 3;
        int tx0  = (tile & 7) << 3;
        int lane = tid & 31;
        int warp = tid >> 5;

        // phase-1: s_in 4x33 rows of stride 36 floats (16B-aligned rows) + s_w1
        // phase-2 overlays s_buf with qk weights (16KB)
        __shared__ __align__(16) char s_buf[31808];   // s_in 19008B + s_w1 12800B
        __shared__ float s_kv[32][65];                // kv tile [c][px], padded
        float* s_in = reinterpret_cast<float*>(s_buf);                 // [ci][33][36]
        float* s_w1 = reinterpret_cast<float*>(s_buf + 19008);         // [ci][25][32]

        float acc[8];
#pragma unroll
        for (int p = 0; p < 8; p++) acc[p] = 0.f;

        int iy0 = ty0 * 4 - 2, ix0 = tx0 * 4 - 2;

        for (int cc = 0; cc < 32; cc += 4) {
            __syncthreads();
            for (int idx = tid; idx < 4 * 25 * 32; idx += 256) {
                int co = idx & 31;
                int k  = (idx >> 5) % 25;
                int ci = idx / (25 * 32);
                s_w1[ci * 800 + k * 32 + co] = tw[(co * 32 + cc + ci) * 25 + k];
            }
            for (int idx = tid; idx < 4 * 33 * 33; idx += 256) {
                int xx = idx % 33;
                int yy = (idx / 33) % 33;
                int ci = idx / (33 * 33);
                int gy = iy0 + yy, gx = ix0 + xx;
                float v = 0.f;
                if ((unsigned)gy < 256u && (unsigned)gx < 256u)
                    v = cen[((b * CH + cc + ci) * 256 + gy) * 256 + gx];
                s_in[ci * 1188 + yy * 36 + xx] = v;
            }
            __syncthreads();
#pragma unroll
            for (int ci = 0; ci < 4; ci++) {
#pragma unroll
                for (int ky = 0; ky < 5; ky++) {
                    // register row cache: 9 LDS.128 cover cols 0..35
                    float r[36];
                    const float4* src = reinterpret_cast<const float4*>(
                        s_in + ci * 1188 + (warp * 4 + ky) * 36);
#pragma unroll
                    for (int q = 0; q < 9; q++)
                        *reinterpret_cast<float4*>(&r[q * 4]) = src[q];
#pragma unroll
                    for (int kx = 0; kx < 5; kx++) {
                        float wv = s_w1[ci * 800 + (ky * 5 + kx) * 32 + lane];
#pragma unroll
                        for (int p = 0; p < 8; p++)
                            acc[p] = fmaf(wv, r[p * 4 + kx], acc[p]);
                    }
                }
            }
        }
        float bias = tb[lane];
#pragma unroll
        for (int p = 0; p < 8; p++)
            s_kv[lane][warp * 8 + p] = acc[p] + bias;   // [channel][px]
        __syncthreads();

        // ---- phase 2: Q/K 1x1 convs on the 64-px tile ----
        float (*s_qkw)[32][32] = reinterpret_cast<float (*)[32][32]>(s_buf); // [var][cc][c]
        for (int idx = tid; idx < 4096; idx += 256) {
            int var = idx >> 10;
            int rem = idx & 1023;
            int cc  = rem >> 5;
            int c   = rem & 31;
            float w = (var == 0) ? qW[c * 32 + cc] : kW[(var - 1) * 1024 + c * 32 + cc];
            s_qkw[var][cc][c] = w;
        }
        __syncthreads();

        int px  = tid & 63;
        int var = tid >> 6;
        float4 a4[8];
#pragma unroll
        for (int c4 = 0; c4 < 8; c4++) a4[c4] = make_float4(0.f, 0.f, 0.f, 0.f);
#pragma unroll 4
        for (int cc = 0; cc < 32; cc++) {
            float x = s_kv[cc][px];
#pragma unroll
            for (int c4 = 0; c4 < 8; c4++) {
                float4 w4 = *reinterpret_cast<float4*>(&s_qkw[var][cc][c4 * 4]);
                a4[c4].x = fmaf(w4.x, x, a4[c4].x);
                a4[c4].y = fmaf(w4.y, x, a4[c4].y);
                a4[c4].z = fmaf(w4.z, x, a4[c4].z);
                a4[c4].w = fmaf(w4.w, x, a4[c4].w);
            }
        }
        int oy = ty0 + (px >> 3), ox = tx0 + (px & 7);
        int plin = oy * 64 + ox;
        float* dst = (var == 0) ? (g_q + b * CH * 4096)
                                : (g_k + ((b * 3 + (var - 1)) * CH) * 4096);
#pragma unroll
        for (int c4 = 0; c4 < 8; c4++) {
            dst[(c4 * 4 + 0) * 4096 + plin] = a4[c4].x;
            dst[(c4 * 4 + 1) * 4096 + plin] = a4[c4].y;
            dst[(c4 * 4 + 2) * 4096 + plin] = a4[c4].z;
            dst[(c4 * 4 + 3) * 4096 + plin] = a4[c4].w;
        }
    } else {
        // ------- k3 body: V_i = value_W[i] @ cen, px-paired f32x2 (zero packs) -------
        int idx   = blockIdx.x - 128;
        int chunk = idx & 63;
        int rest  = idx >> 6;          // 0..11
        int iv    = rest % 6;
        int b     = rest / 6;
        int i     = iv >> 1, half = iv & 1;
        int p4    = (chunk * 256 + tid) * 4;

        __shared__ __align__(8) float2 s_w3[32][16];  // [cc][c_local] = (w, w)
        for (int t = tid; t < 512; t += 256) {
            int c = t & 15, cc = t >> 4;
            float w = vW[((i * CH + half * 16 + c) * CH) + cc];
            s_w3[cc][c] = make_float2(w, w);
        }
        __syncthreads();

        ull acc2[16][2];   // [c][pxpair]: lanes = (px0,px1) / (px2,px3)
#pragma unroll
        for (int c = 0; c < 16; c++) { acc2[c][0] = 0ull; acc2[c][1] = 0ull; }

        const float* base = cen + (size_t)b * CH * 65536 + p4;
#pragma unroll
        for (int cc0 = 0; cc0 < 32; cc0 += 4) {
            ulonglong2 xb[4];
#pragma unroll
            for (int u = 0; u < 4; u++)
                xb[u] = *reinterpret_cast<const ulonglong2*>(base + (cc0 + u) * 65536);
#pragma unroll
            for (int u = 0; u < 4; u++) {
                const ull* wrow = reinterpret_cast<const ull*>(s_w3[cc0 + u]);
#pragma unroll
                for (int c = 0; c < 16; c++) {
                    ull wp = wrow[c];
                    FMA2(acc2[c][0], wp, xb[u].x, acc2[c][0]);
                    FMA2(acc2[c][1], wp, xb[u].y, acc2[c][1]);
                }
            }
        }
#pragma unroll
        for (int c = 0; c < 16; c++) {
            float f0, f1, f2, f3;
            UNPACK_FF(f0, f1, acc2[c][0]);
            UNPACK_FF(f2, f3, acc2[c][1]);
            *reinterpret_cast<float4*>(
                &g_V[((b * 3 + i) * CH + half * 16 + c) * 65536 + p4]) =
                make_float4(f0, f1, f2, f3);
        }
    }
}

// ================= K2b: raw score sums, one block per (b,c,i) ================
__global__ void __launch_bounds__(256) k2b_raw() {
    int c = blockIdx.x, i = blockIdx.y, b = blockIdx.z;
    __shared__ float sQ[4096];
    __shared__ float sK[4096];
    __shared__ float s_part[17][8];
    int tid = threadIdx.x;
    int lane = tid & 31, warp = tid >> 5;
    constexpr int DY[8] = {-1, -1, -1, 0, 1, 1, 1, 0};
    constexpr int DX[8] = {-1, 0, 1, 1, 1, 0, -1, -1};
    constexpr int SH[3] = {1, 2, 4};

    float qn = 0.f;
    for (int p = tid; p < 4096; p += 256) {
        float a = g_q[(b * CH + c) * 4096 + p];
        sQ[p] = a;
        qn = fmaf(a, a, qn);
        sK[p] = g_k[((b * 3 + i) * CH + c) * 4096 + p];
    }
    __syncthreads();

    int d = SH[i];
    float skk[8], sqk[8];
#pragma unroll
    for (int j = 0; j < 8; j++) { skk[j] = 0.f; sqk[j] = 0.f; }
    for (int p = tid; p < 4096; p += 256) {
        int y = p >> 6, x = p & 63;
        float kc = sK[p];
        float qv = sQ[p];
#pragma unroll
        for (int j = 0; j < 8; j++) {
            int ny = y + DY[j] * d, nx = x + DX[j] * d;
            float nb = ((unsigned)ny < 64u && (unsigned)nx < 64u)
                           ? sK[ny * 64 + nx] : 0.f;
            float v = kc - nb;
            skk[j] = fmaf(v, v, skk[j]);
            sqk[j] = fmaf(qv, v, sqk[j]);
        }
    }
#pragma unroll
    for (int j = 0; j < 8; j++) {
        skk[j] = warpReduce(skk[j]);
        sqk[j] = warpReduce(sqk[j]);
    }
    qn = warpReduce(qn);
    if (lane == 0) {
#pragma unroll
        for (int j = 0; j < 8; j++) {
            s_part[j][warp]     = skk[j];
            s_part[8 + j][warp] = sqk[j];
        }
        s_part[16][warp] = qn;
    }
    __syncthreads();
    if (tid < 17) {
        float s = 0.f;
        for (int w = 0; w < 8; w++) s += s_part[tid][w];
        int bc = b * 32 + c;
        if (tid < 16)       g_sraw[bc * 48 + i * 16 + tid] = s;
        else if (i == 0)    g_sqq[bc] = s;
    }
}

// ================= K4v: 27-tap stencil, float4, inline score normalize ================
__device__ __forceinline__ void load12(float* w, const float* row, int x4) {
    float4 a = (x4 >= 4)   ? *reinterpret_cast<const float4*>(row + x4 - 4)
                           : make_float4(0.f, 0.f, 0.f, 0.f);
    float4 bq =              *reinterpret_cast<const float4*>(row + x4);
    float4 cq = (x4 <= 248) ? *reinterpret_cast<const float4*>(row + x4 + 4)
                            : make_float4(0.f, 0.f, 0.f, 0.f);
    w[0] = a.x;  w[1] = a.y;  w[2] = a.z;  w[3] = a.w;
    w[4] = bq.x; w[5] = bq.y; w[6] = bq.z; w[7] = bq.w;
    w[8] = cq.x; w[9] = cq.y; w[10] = cq.z; w[11] = cq.w;
}

__global__ void __launch_bounds__(256) k4v() {
    int c = blockIdx.y, b = blockIdx.z;
    int bc = b * 32 + c;
    __shared__ float s_s[24];
    __shared__ float s_A[3];
    int tid = threadIdx.x;

    if (tid < 24) {
        int i = tid >> 3, j = tid & 7;
        float skk = g_sraw[bc * 48 + i * 16 + j];
        float sqk = g_sraw[bc * 48 + i * 16 + 8 + j];
        float qd = fmaxf(sqrtf(g_sqq[bc]), 1e-12f);
        float kd = fmaxf(sqrtf(skk), 1e-12f);
        s_s[tid] = sqk / (qd * kd);
    }
    __syncthreads();
    if (tid == 0) {
        float ss = 0.f;
        for (int m = 0; m < 24; m++) ss = fmaf(s_s[m], s_s[m], ss);
        float inv = 1.f / fmaxf(sqrtf(ss), 1e-12f);
        float a0 = 0.f, a1 = 0.f, a2 = 0.f;
        for (int m = 0; m < 24; m++) s_s[m] *= inv;
        for (int j = 0; j < 8; j++) { a0 += s_s[j]; a1 += s_s[8 + j]; a2 += s_s[16 + j]; }
        s_A[0] = a0; s_A[1] = a1; s_A[2] = a2;
    }
    __syncthreads();

    constexpr int SH[3] = {1, 2, 4};
    int p4 = (blockIdx.x * 256 + tid) * 4;
    int y = p4 >> 8, x4 = p4 & 255;

    const float* Vb = g_V + ((size_t)(b * 3) * CH + c) * 65536;
    float4 o = make_float4(0.f, 0.f, 0.f, 0.f);
    float* ol = reinterpret_cast<float*>(&o);

#pragma unroll
    for (int i = 0; i < 3; i++) {
        const float* V = Vb + (size_t)i * CH * 65536;
        const int d = SH[i];
        float w[12];
        // center row: A_i * center - s[3]*(dx=+d) - s[7]*(dx=-d)
        load12(w, V + y * 256, x4);
        float A  = s_A[i];
        float s3 = s_s[i * 8 + 3], s7 = s_s[i * 8 + 7];
#pragma unroll
        for (int l = 0; l < 4; l++) {
            float t = A * w[4 + l];
            t = fmaf(-s3, w[4 + l + d], t);
            t = fmaf(-s7, w[4 + l - d], t);
            ol[l] += t;
        }
        int ny = y - d;
        if (ny >= 0) {
            load12(w, V + ny * 256, x4);
            float s0 = s_s[i * 8 + 0], s1 = s_s[i * 8 + 1], s2 = s_s[i * 8 + 2];
#pragma unroll
            for (int l = 0; l < 4; l++) {
                float t = fmaf(-s0, w[4 + l - d], 0.f);
                t = fmaf(-s1, w[4 + l], t);
                t = fmaf(-s2, w[4 + l + d], t);
                ol[l] += t;
            }
        }
        ny = y + d;
        if (ny < 256) {
            load12(w, V + ny * 256, x4);
            float s4 = s_s[i * 8 + 4], s5 = s_s[i * 8 + 5], s6 = s_s[i * 8 + 6];
#pragma unroll
            for (int l = 0; l < 4; l++) {
                float t = fmaf(-s4, w[4 + l + d], 0.f);
                t = fmaf(-s5, w[4 + l], t);
                t = fmaf(-s6, w[4 + l - d], t);
                ol[l] += t;
            }
        }
    }
    *reinterpret_cast<float4*>(&g_pre[(size_t)bc * 65536 + p4]) = o;
}

// ================= K5v: out 1x1 conv + BN + ReLU, px-paired f32x2, 8-co split ================
// grid: (64 px-chunks, 4 co-quarters, 2 b), 256 thr; thread = 4 px, 8 out channels
__global__ void __launch_bounds__(256) k5v(const float* __restrict__ oW,
                                           const float* __restrict__ gm,
                                           const float* __restrict__ bt,
                                           const float* __restrict__ mn,
                                           const float* __restrict__ vr,
                                           float* __restrict__ out) {
    int quarter = blockIdx.y, b = blockIdx.z;
    int tid = threadIdx.x;
    int p4 = (blockIdx.x * 256 + tid) * 4;

    __shared__ __align__(8) float2 s_w[32][8];   // [c][co_local] = (w, w)
    __shared__ float s_g[8], s_bb[8];
    if (tid < 256) {
        int co = tid & 7, c = tid >> 3;
        float w = oW[(quarter * 8 + co) * 32 + c];
        s_w[c][co] = make_float2(w, w);
    }
    if (tid < 8) {
        int co = quarter * 8 + tid;
        float inv = rsqrtf(vr[co] + 1e-5f);
        float g = gm[co] * inv;
        s_g[tid]  = g;
        s_bb[tid] = bt[co] - mn[co] * g;
    }
    __syncthreads();

    ull acc2[8][2];  // [co][pxpair]
#pragma unroll
    for (int co = 0; co < 8; co++) { acc2[co][0] = 0ull; acc2[co][1] = 0ull; }

    const float* base = g_pre + (size_t)b * CH * 65536 + p4;
#pragma unroll
    for (int c0 = 0; c0 < 32; c0 += 4) {
        ulonglong2 xb[4];
#pragma unroll
        for (int u = 0; u < 4; u++)
            xb[u] = *reinterpret_cast<const ulonglong2*>(base + (c0 + u) * 65536);
#pragma unroll
        for (int u = 0; u < 4; u++) {
            const ull* wrow = reinterpret_cast<const ull*>(s_w[c0 + u]);
#pragma unroll
            for (int co = 0; co < 8; co++) {
                ull wp = wrow[co];
                FMA2(acc2[co][0], wp, xb[u].x, acc2[co][0]);
                FMA2(acc2[co][1], wp, xb[u].y, acc2[co][1]);
            }
        }
    }
#pragma unroll
    for (int co = 0; co < 8; co++) {
        float f0, f1, f2, f3;
        UNPACK_FF(f0, f1, acc2[co][0]);
        UNPACK_FF(f2, f3, acc2[co][1]);
        float g = s_g[co], bb = s_bb[co];
        float4 r;
        r.x = fmaxf(fmaf(f0, g, bb), 0.f);
        r.y = fmaxf(fmaf(f1, g, bb), 0.f);
        r.z = fmaxf(fmaf(f2, g, bb), 0.f);
        r.w = fmaxf(fmaf(f3, g, bb), 0.f);
        *reinterpret_cast<float4*>(
            &out[((size_t)(b * CH + quarter * 8 + co)) * 65536 + p4]) = r;
    }
}

// ---------------- launch ----------------
extern "C" void kernel_launch(void* const* d_in, const int* in_sizes, int n_in,
                              void* d_out, int out_size) {
    const float* cen     = (const float*)d_in[0];
    const float* trans_W = (const float*)d_in[1];
    const float* trans_b = (const float*)d_in[2];
    const float* query_W = (const float*)d_in[3];
    const float* value_W = (const float*)d_in[4];
    const float* key_W   = (const float*)d_in[5];
    const float* out_W   = (const float*)d_in[6];
    const float* bn_g    = (const float*)d_in[7];
    const float* bn_b    = (const float*)d_in[8];
    const float* bn_m    = (const float*)d_in[9];
    const float* bn_v    = (const float*)d_in[10];
    float* out = (float*)d_out;

    kA      <<<896, 256>>>(cen, trans_W, trans_b, query_W, key_W, value_W);
    k2b_raw <<<dim3(32, 3, 2), 256>>>();
    k4v     <<<dim3(64, 32, 2), 256>>>();
    k5v     <<<dim3(64, 4, 2), 256>>>(out_W, bn_g, bn_b, bn_m, bn_v, out);
}

// round 16
// speedup vs baseline: 1.0547x; 1.0547x over previous
#include <cuda_runtime.h>
#include <cuda_bf16.h>

#define CH 32

// ---------------- device scratch (static: no allocation) ----------------
__device__ float g_q   [2 * CH * 4096];            // query field  [b][c][4096]
__device__ float g_k   [2 * 3 * CH * 4096];        // key fields   [b][i][c][4096]
__device__ float g_sraw[2 * CH * 48];              // raw sums: [b*32+c][i*16 + (0..7 skk | 8..15 sqk)]
__device__ float g_sqq [2 * CH];                   // ||Q||^2 per (b,c)
__device__ float g_V   [2 * 3 * CH * 65536];       // value fields [b][i][c][65536]
__device__ float g_pre [2 * CH * 65536];           // pre out-conv [b][c][65536]

__device__ __forceinline__ float warpReduce(float v) {
#pragma unroll
    for (int o = 16; o > 0; o >>= 1) v += __shfl_down_sync(0xffffffffu, v, o);
    return v;
}

// ================= Kernel A: k1(trans conv + Q/K epilogue)  ||  k3(value GEMMs) ================
// grid.x: [0,128) -> k1 body, [128,896) -> k3 body. 256 threads.
__global__ void __launch_bounds__(256) kA(const float* __restrict__ cen,
                                          const float* __restrict__ tw,
                                          const float* __restrict__ tb,
                                          const float* __restrict__ qW,
                                          const float* __restrict__ kW,
                                          const float* __restrict__ vW) {
    int tid = threadIdx.x;
    if (blockIdx.x < 128) {
        // ---------------- k1 body: 5x5 stride-4 conv, then Q/K 1x1 on the tile ----------------
        int bt   = blockIdx.x;
        int b    = bt >> 6;
        int tile = bt & 63;
        int ty0  = (tile >> 3) << 3;
        int tx0  = (tile & 7) << 3;
        int lane = tid & 31;
        int warp = tid >> 5;

        __shared__ __align__(16) char s_buf[30224];   // s_in 17424B + s_w 12800B
        __shared__ float s_kv[32][65];                // kv tile [c][px], padded
        float (*s_in)[33][33] = reinterpret_cast<float (*)[33][33]>(s_buf);
        float (*s_w1)[25][32] = reinterpret_cast<float (*)[25][32]>(s_buf + 17424);

        float acc[8];
#pragma unroll
        for (int p = 0; p < 8; p++) acc[p] = 0.f;

        int iy0 = ty0 * 4 - 2, ix0 = tx0 * 4 - 2;

        for (int cc = 0; cc < 32; cc += 4) {
            __syncthreads();
            for (int idx = tid; idx < 4 * 25 * 32; idx += 256) {
                int co = idx & 31;
                int k  = (idx >> 5) % 25;
                int ci = idx / (25 * 32);
                s_w1[ci][k][co] = tw[(co * 32 + cc + ci) * 25 + k];
            }
            for (int idx = tid; idx < 4 * 33 * 33; idx += 256) {
                int xx = idx % 33;
                int yy = (idx / 33) % 33;
                int ci = idx / (33 * 33);
                int gy = iy0 + yy, gx = ix0 + xx;
                float v = 0.f;
                if ((unsigned)gy < 256u && (unsigned)gx < 256u)
                    v = cen[((b * CH + cc + ci) * 256 + gy) * 256 + gx];
                s_in[ci][yy][xx] = v;
            }
            __syncthreads();
#pragma unroll
            for (int ci = 0; ci < 4; ci++)
#pragma unroll
                for (int ky = 0; ky < 5; ky++)
#pragma unroll
                    for (int kx = 0; kx < 5; kx++) {
                        float wv = s_w1[ci][ky * 5 + kx][lane];
#pragma unroll
                        for (int p = 0; p < 8; p++)
                            acc[p] = fmaf(wv, s_in[ci][warp * 4 + ky][p * 4 + kx], acc[p]);
                    }
        }
        float bias = tb[lane];
#pragma unroll
        for (int p = 0; p < 8; p++)
            s_kv[lane][warp * 8 + p] = acc[p] + bias;   // [channel][px]
        __syncthreads();

        // ---- phase 2: Q/K 1x1 convs on the 64-px tile ----
        float (*s_qkw)[32][32] = reinterpret_cast<float (*)[32][32]>(s_buf); // [var][cc][c]
        for (int idx = tid; idx < 4096; idx += 256) {
            int var = idx >> 10;
            int rem = idx & 1023;
            int cc  = rem >> 5;
            int c   = rem & 31;
            float w = (var == 0) ? qW[c * 32 + cc] : kW[(var - 1) * 1024 + c * 32 + cc];
            s_qkw[var][cc][c] = w;
        }
        __syncthreads();

        int px  = tid & 63;
        int var = tid >> 6;
        float4 a4[8];
#pragma unroll
        for (int c4 = 0; c4 < 8; c4++) a4[c4] = make_float4(0.f, 0.f, 0.f, 0.f);
#pragma unroll 4
        for (int cc = 0; cc < 32; cc++) {
            float x = s_kv[cc][px];
#pragma unroll
            for (int c4 = 0; c4 < 8; c4++) {
                float4 w4 = *reinterpret_cast<float4*>(&s_qkw[var][cc][c4 * 4]);
                a4[c4].x = fmaf(w4.x, x, a4[c4].x);
                a4[c4].y = fmaf(w4.y, x, a4[c4].y);
                a4[c4].z = fmaf(w4.z, x, a4[c4].z);
                a4[c4].w = fmaf(w4.w, x, a4[c4].w);
            }
        }
        int oy = ty0 + (px >> 3), ox = tx0 + (px & 7);
        int plin = oy * 64 + ox;
        float* dst = (var == 0) ? (g_q + b * CH * 4096)
                                : (g_k + ((b * 3 + (var - 1)) * CH) * 4096);
#pragma unroll
        for (int c4 = 0; c4 < 8; c4++) {
            dst[(c4 * 4 + 0) * 4096 + plin] = a4[c4].x;
            dst[(c4 * 4 + 1) * 4096 + plin] = a4[c4].y;
            dst[(c4 * 4 + 2) * 4096 + plin] = a4[c4].z;
            dst[(c4 * 4 + 3) * 4096 + plin] = a4[c4].w;
        }
    } else {
        // ---------------- k3 body: V_i = value_W[i] @ cen, float4, 16-ch split ----------------
        int idx   = blockIdx.x - 128;
        int chunk = idx & 63;
        int rest  = idx >> 6;          // 0..11
        int iv    = rest % 6;
        int b     = rest / 6;
        int i     = iv >> 1, half = iv & 1;
        int p4    = (chunk * 256 + tid) * 4;

        __shared__ float s_w3[32][16];  // [cc][c_local]
        for (int t = tid; t < 512; t += 256) {
            int c = t & 15, cc = t >> 4;
            s_w3[cc][c] = vW[((i * CH + half * 16 + c) * CH) + cc];
        }
        __syncthreads();

        float4 acc[16];
#pragma unroll
        for (int c = 0; c < 16; c++) acc[c] = make_float4(0.f, 0.f, 0.f, 0.f);

        const float* base = cen + (size_t)b * CH * 65536 + p4;
#pragma unroll
        for (int cc0 = 0; cc0 < 32; cc0 += 4) {
            float4 xb[4];
#pragma unroll
            for (int u = 0; u < 4; u++)
                xb[u] = *reinterpret_cast<const float4*>(base + (cc0 + u) * 65536);
#pragma unroll
            for (int u = 0; u < 4; u++) {
                int cc = cc0 + u;
#pragma unroll
                for (int c = 0; c < 16; c++) {
                    float w = s_w3[cc][c];
                    acc[c].x = fmaf(w, xb[u].x, acc[c].x);
                    acc[c].y = fmaf(w, xb[u].y, acc[c].y);
                    acc[c].z = fmaf(w, xb[u].z, acc[c].z);
                    acc[c].w = fmaf(w, xb[u].w, acc[c].w);
                }
            }
        }
#pragma unroll
        for (int c = 0; c < 16; c++)
            *reinterpret_cast<float4*>(
                &g_V[((b * 3 + i) * CH + half * 16 + c) * 65536 + p4]) = acc[c];
    }
}

// ================= K2b: raw score sums, one block per (b,c,i) ================
__global__ void __launch_bounds__(256) k2b_raw() {
    int c = blockIdx.x, i = blockIdx.y, b = blockIdx.z;
    __shared__ float sQ[4096];
    __shared__ float sK[4096];
    __shared__ float s_part[17][8];
    int tid = threadIdx.x;
    int lane = tid & 31, warp = tid >> 5;
    constexpr int DY[8] = {-1, -1, -1, 0, 1, 1, 1, 0};
    constexpr int DX[8] = {-1, 0, 1, 1, 1, 0, -1, -1};
    constexpr int SH[3] = {1, 2, 4};

    float qn = 0.f;
    for (int p = tid; p < 4096; p += 256) {
        float a = g_q[(b * CH + c) * 4096 + p];
        sQ[p] = a;
        qn = fmaf(a, a, qn);
        sK[p] = g_k[((b * 3 + i) * CH + c) * 4096 + p];
    }
    __syncthreads();

    int d = SH[i];
    float skk[8], sqk[8];
#pragma unroll
    for (int j = 0; j < 8; j++) { skk[j] = 0.f; sqk[j] = 0.f; }
    for (int p = tid; p < 4096; p += 256) {
        int y = p >> 6, x = p & 63;
        float kc = sK[p];
        float qv = sQ[p];
#pragma unroll
        for (int j = 0; j < 8; j++) {
            int ny = y + DY[j] * d, nx = x + DX[j] * d;
            float nb = ((unsigned)ny < 64u && (unsigned)nx < 64u)
                           ? sK[ny * 64 + nx] : 0.f;
            float v = kc - nb;
            skk[j] = fmaf(v, v, skk[j]);
            sqk[j] = fmaf(qv, v, sqk[j]);
        }
    }
#pragma unroll
    for (int j = 0; j < 8; j++) {
        skk[j] = warpReduce(skk[j]);
        sqk[j] = warpReduce(sqk[j]);
    }
    qn = warpReduce(qn);
    if (lane == 0) {
#pragma unroll
        for (int j = 0; j < 8; j++) {
            s_part[j][warp]     = skk[j];
            s_part[8 + j][warp] = sqk[j];
        }
        s_part[16][warp] = qn;
    }
    __syncthreads();
    if (tid < 17) {
        float s = 0.f;
        for (int w = 0; w < 8; w++) s += s_part[tid][w];
        int bc = b * 32 + c;
        if (tid < 16)       g_sraw[bc * 48 + i * 16 + tid] = s;
        else if (i == 0)    g_sqq[bc] = s;
    }
}

// ================= K4v: 27-tap stencil, register-blocked 4x8 px/thread ================
__device__ __forceinline__ void load12(float* w, const float* row, int x4) {
    float4 a = (x4 >= 4)   ? *reinterpret_cast<const float4*>(row + x4 - 4)
                           : make_float4(0.f, 0.f, 0.f, 0.f);
    float4 bq =              *reinterpret_cast<const float4*>(row + x4);
    float4 cq = (x4 <= 248) ? *reinterpret_cast<const float4*>(row + x4 + 4)
                            : make_float4(0.f, 0.f, 0.f, 0.f);
    w[0] = a.x;  w[1] = a.y;  w[2] = a.z;  w[3] = a.w;
    w[4] = bq.x; w[5] = bq.y; w[6] = bq.z; w[7] = bq.w;
    w[8] = cq.x; w[9] = cq.y; w[10] = cq.z; w[11] = cq.w;
}

// One dilation plane: walk rows y0-d .. y0+7+d once; each row-window in registers
// serves the center taps of its own row plus the upper/lower taps of rows +-d.
// Per-pixel accumulation order (center, upper, lower per i) identical to before.
template<int d>
__device__ __forceinline__ void stencil_i(const float* __restrict__ V,
                                          const float* __restrict__ s, float A,
                                          float (&acc)[8][4], int y0, int x4) {
    float s0 = s[0], s1 = s[1], s2 = s[2], s3 = s[3];
    float s4 = s[4], s5 = s[5], s6 = s[6], s7 = s[7];
#pragma unroll
    for (int ry = -d; ry <= 7 + d; ry++) {
        int y = y0 + ry;
        float w[12];
        if ((unsigned)y < 256u) {
            load12(w, V + y * 256, x4);
        } else {
#pragma unroll
            for (int q = 0; q < 12; q++) w[q] = 0.f;
        }
        if (ry >= 0 && ry < 8) {           // center row of output ry
#pragma unroll
            for (int l = 0; l < 4; l++) {
                float t = A * w[4 + l];
                t = fmaf(-s3, w[4 + l + d], t);
                t = fmaf(-s7, w[4 + l - d], t);
                acc[ry][l] += t;
            }
        }
        if (ry + d < 8) {                  // upper-neighbor row for output ry+d
#pragma unroll
            for (int l = 0; l < 4; l++) {
                float t = fmaf(-s0, w[4 + l - d], 0.f);
                t = fmaf(-s1, w[4 + l], t);
                t = fmaf(-s2, w[4 + l + d], t);
                acc[ry + d][l] += t;
            }
        }
        if (ry - d >= 0) {                 // lower-neighbor row for output ry-d
#pragma unroll
            for (int l = 0; l < 4; l++) {
                float t = fmaf(-s4, w[4 + l + d], 0.f);
                t = fmaf(-s5, w[4 + l], t);
                t = fmaf(-s6, w[4 + l - d], t);
                acc[ry - d][l] += t;
            }
        }
    }
}

// grid: (8 y-tiles of 32 rows, 32 c, 2 b), 256 thr; thread = 4 wide x 8 tall px
__global__ void __launch_bounds__(256) k4v() {
    int c = blockIdx.y, b = blockIdx.z;
    int bc = b * 32 + c;
    __shared__ float s_s[24];
    __shared__ float s_A[3];
    int tid = threadIdx.x;

    if (tid < 24) {
        int i = tid >> 3, j = tid & 7;
        float skk = g_sraw[bc * 48 + i * 16 + j];
        float sqk = g_sraw[bc * 48 + i * 16 + 8 + j];
        float qd = fmaxf(sqrtf(g_sqq[bc]), 1e-12f);
        float kd = fmaxf(sqrtf(skk), 1e-12f);
        s_s[tid] = sqk / (qd * kd);
    }
    __syncthreads();
    if (tid == 0) {
        float ss = 0.f;
        for (int m = 0; m < 24; m++) ss = fmaf(s_s[m], s_s[m], ss);
        float inv = 1.f / fmaxf(sqrtf(ss), 1e-12f);
        float a0 = 0.f, a1 = 0.f, a2 = 0.f;
        for (int m = 0; m < 24; m++) s_s[m] *= inv;
        for (int j = 0; j < 8; j++) { a0 += s_s[j]; a1 += s_s[8 + j]; a2 += s_s[16 + j]; }
        s_A[0] = a0; s_A[1] = a1; s_A[2] = a2;
    }
    __syncthreads();

    int xg = tid & 63;           // x-group: 4 px
    int ys = tid >> 6;           // y-strip: 0..3
    int x4 = xg * 4;
    int y0 = blockIdx.x * 32 + ys * 8;

    const float* Vb = g_V + ((size_t)(b * 3) * CH + c) * 65536;

    float acc[8][4];
#pragma unroll
    for (int r = 0; r < 8; r++)
#pragma unroll
        for (int l = 0; l < 4; l++) acc[r][l] = 0.f;

    stencil_i<1>(Vb,                          s_s,      s_A[0], acc, y0, x4);
    stencil_i<2>(Vb + (size_t)CH * 65536,     s_s + 8,  s_A[1], acc, y0, x4);
    stencil_i<4>(Vb + (size_t)2 * CH * 65536, s_s + 16, s_A[2], acc, y0, x4);

    float* dst = g_pre + (size_t)bc * 65536 + y0 * 256 + x4;
#pragma unroll
    for (int r = 0; r < 8; r++)
        *reinterpret_cast<float4*>(dst + r * 256) =
            make_float4(acc[r][0], acc[r][1], acc[r][2], acc[r][3]);
}

// ================= K5v: out 1x1 conv + BN + ReLU, float4, 16-co split ================
__global__ void __launch_bounds__(256) k5v(const float* __restrict__ oW,
                                           const float* __restrict__ gm,
                                           const float* __restrict__ bt,
                                           const float* __restrict__ mn,
                                           const float* __restrict__ vr,
                                           float* __restrict__ out) {
    int half = blockIdx.y, b = blockIdx.z;
    int tid = threadIdx.x;
    int p4 = (blockIdx.x * 256 + tid) * 4;

    __shared__ float s_w[32][16];   // [c][co_local]
    __shared__ float s_g[16], s_bb[16];
    for (int t = tid; t < 512; t += 256) {
        int co = t & 15, c = t >> 4;
        s_w[c][co] = oW[(half * 16 + co) * 32 + c];
    }
    if (tid < 16) {
        int co = half * 16 + tid;
        float inv = rsqrtf(vr[co] + 1e-5f);
        float g = gm[co] * inv;
        s_g[tid]  = g;
        s_bb[tid] = bt[co] - mn[co] * g;
    }
    __syncthreads();

    float4 acc[16];
#pragma unroll
    for (int co = 0; co < 16; co++) acc[co] = make_float4(0.f, 0.f, 0.f, 0.f);

    const float* base = g_pre + (size_t)b * CH * 65536 + p4;
#pragma unroll
    for (int c0 = 0; c0 < 32; c0 += 4) {
        float4 xb[4];
#pragma unroll
        for (int u = 0; u < 4; u++)
            xb[u] = *reinterpret_cast<const float4*>(base + (c0 + u) * 65536);
#pragma unroll
        for (int u = 0; u < 4; u++) {
            int c = c0 + u;
#pragma unroll
            for (int co = 0; co < 16; co++) {
                float w = s_w[c][co];
                acc[co].x = fmaf(w, xb[u].x, acc[co].x);
                acc[co].y = fmaf(w, xb[u].y, acc[co].y);
                acc[co].z = fmaf(w, xb[u].z, acc[co].z);
                acc[co].w = fmaf(w, xb[u].w, acc[co].w);
            }
        }
    }
#pragma unroll
    for (int co = 0; co < 16; co++) {
        float g = s_g[co], bb = s_bb[co];
        float4 r;
        r.x = fmaxf(fmaf(acc[co].x, g, bb), 0.f);
        r.y = fmaxf(fmaf(acc[co].y, g, bb), 0.f);
        r.z = fmaxf(fmaf(acc[co].z, g, bb), 0.f);
        r.w = fmaxf(fmaf(acc[co].w, g, bb), 0.f);
        *reinterpret_cast<float4*>(
            &out[((size_t)(b * CH + half * 16 + co)) * 65536 + p4]) = r;
    }
}

// ---------------- launch ----------------
extern "C" void kernel_launch(void* const* d_in, const int* in_sizes, int n_in,
                              void* d_out, int out_size) {
    const float* cen     = (const float*)d_in[0];
    const float* trans_W = (const float*)d_in[1];
    const float* trans_b = (const float*)d_in[2];
    const float* query_W = (const float*)d_in[3];
    const float* value_W = (const float*)d_in[4];
    const float* key_W   = (const float*)d_in[5];
    const float* out_W   = (const float*)d_in[6];
    const float* bn_g    = (const float*)d_in[7];
    const float* bn_b    = (const float*)d_in[8];
    const float* bn_m    = (const float*)d_in[9];
    const float* bn_v    = (const float*)d_in[10];
    float* out = (float*)d_out;

    kA      <<<896, 256>>>(cen, trans_W, trans_b, query_W, key_W, value_W);
    k2b_raw <<<dim3(32, 3, 2), 256>>>();
    k4v     <<<dim3(8, 32, 2), 256>>>();
    k5v     <<<dim3(64, 2, 2), 256>>>(out_W, bn_g, bn_b, bn_m, bn_v, out);
}